// round 13
// baseline (speedup 1.0000x reference)
#include <cuda_runtime.h>
#include <cuda_fp16.h>
#include <cstdint>

#define Bb 32
#define Nn 1024
#define Tt 32
#define Ff 5
#define Hh 64
#define Rr 5
#define BN (Bb*Nn)
#define NSEQ 64

// Scratch
__device__ float g_eold[(size_t)BN * Hh];
__device__ float g_coef[(size_t)Nn * Nn];
__device__ float g_deg[Nn];

__device__ __forceinline__ float tanha(float x) {
    float y; asm("tanh.approx.f32 %0, %1;" : "=f"(y) : "f"(x)); return y;
}
__device__ __forceinline__ __half2 tanh_h2(__half2 x) {
    uint32_t xi = *(uint32_t*)&x, yi;
    asm("tanh.approx.f16x2 %0, %1;" : "=r"(yi) : "r"(xi));
    return *(__half2*)&yi;
}
__device__ __forceinline__ uint32_t smem_u32(const void* p) {
    uint32_t a;
    asm("{ .reg .u64 t; cvta.to.shared.u64 t, %1; cvt.u32.u64 %0, t; }" : "=r"(a) : "l"(p));
    return a;
}
__device__ __forceinline__ uint32_t pack_h2(float lo, float hi) {
    __half2 h = __floats2half2_rn(lo, hi);
    return *(uint32_t*)&h;
}

// fp16 MMA: D[16,8] += A[16,16] * B[16,8], f32 accum
#define MMA_F16(D, A, B) \
    asm volatile("mma.sync.aligned.m16n8k16.row.col.f32.f16.f16.f32 " \
        "{%0,%1,%2,%3}, {%4,%5,%6,%7}, {%8,%9}, {%0,%1,%2,%3};" \
        : "+f"((D)[0]), "+f"((D)[1]), "+f"((D)[2]), "+f"((D)[3]) \
        : "r"((A)[0]), "r"((A)[1]), "r"((A)[2]), "r"((A)[3]), \
          "r"((B)[0]), "r"((B)[1]))

#define LDSM4(r, addr) \
    asm volatile("ldmatrix.sync.aligned.m8n8.x4.shared.b16 {%0,%1,%2,%3}, [%4];" \
        : "=r"((r)[0]), "=r"((r)[1]), "=r"((r)[2]), "=r"((r)[3]) : "r"(addr))
#define LDSM4T(r, addr) \
    asm volatile("ldmatrix.sync.aligned.m8n8.x4.trans.shared.b16 {%0,%1,%2,%3}, [%4];" \
        : "=r"((r)[0]), "=r"((r)[1]), "=r"((r)[2]), "=r"((r)[3]) : "r"(addr))

// ---- LSTM smem layout (byte offsets); A row = 88 halves ----
#define ASTH   88
#define AS0_B  0
#define AS1_B  11264
#define XH_B   22528
#define SP_B   (XH_B + 20480)
#define WN_B   (SP_B + 2048)
#define AW_B   (WN_B + 256)
#define DYN_SMEM (AW_B + 256)

// ---- GNN smem layout (byte offsets) ----
#define GJT    64
#define EJH_ST 88
#define SH_ST  72
#define CF_ST  68
#define G_EJ_B 0
#define G_SH_B 11264
#define G_CF_B (11264 + 18432)
#define GNN_SMEM (G_CF_B + 34816)

// ---------------------------------------------------------------------------
// Kernel 1: edge gates
// ---------------------------------------------------------------------------
__global__ __launch_bounds__(256) void prep_kernel(
    const float* __restrict__ A,
    const float* __restrict__ gnn_w,
    const float* __restrict__ gnn_b)
{
    const int i = blockIdx.x;
    const float gw0 = gnn_w[0], gw1 = gnn_w[1], gw2 = gnn_w[2],
                gw3 = gnn_w[3], gw4 = gnn_w[4];
    const float gb = gnn_b[0];
    float degloc = 0.f;
    for (int j = threadIdx.x; j < Nn; j += 256) {
        const float* a = A + ((size_t)i * Nn + j) * Rr;
        float a0 = a[0], a1 = a[1], a2 = a[2], a3 = a[3], a4 = a[4];
        float s = a0 + a1 + a2 + a3 + a4;
        float z = gb + a0 * gw0 + a1 * gw1 + a2 * gw2 + a3 * gw3 + a4 * gw4;
        float w = z > 0.f ? z : 0.2f * z;
        float m = s > 0.f ? 1.f : 0.f;
        g_coef[(size_t)i * Nn + j] = m * w;
        degloc += m;
    }
    __shared__ float red[256];
    red[threadIdx.x] = degloc;
    __syncthreads();
    for (int o = 128; o > 0; o >>= 1) {
        if (threadIdx.x < o) red[threadIdx.x] += red[threadIdx.x + o];
        __syncthreads();
    }
    if (threadIdx.x == 0) g_deg[i] = red[0];
}

// ---------------------------------------------------------------------------
// LSTM phase 1: MMA + f16x2 packed activations (5 MUFU per element-PAIR)
// ---------------------------------------------------------------------------
template<int R>
__device__ __forceinline__ void lstm_phase1(
    uint32_t lm_off, const uint32_t (&bf)[4][5][2], float (&c_)[16], float (&hr)[16])
{
    const __half2 hhalf = __float2half2_rn(0.5f);
#pragma unroll
    for (int mti = 0; mti < 4; mti++) {
        const int mt = (mti + R) & 3;
        float d[4][4];
#pragma unroll
        for (int nt = 0; nt < 4; nt++) {
            d[nt][0] = 0.f; d[nt][1] = 0.f; d[nt][2] = 0.f; d[nt][3] = 0.f;
        }
        const uint32_t mb = lm_off + (uint32_t)mt * 16 * (ASTH * 2);
#pragma unroll
        for (int kt = 0; kt < 5; kt++) {
            uint32_t a[4];
            LDSM4(a, mb + kt * 32);
#pragma unroll
            for (int nt = 0; nt < 4; nt++)
                MMA_F16(d[nt], a, bf[nt][kt]);
        }
        // packed activations: pairs (e0,e1) = (0,1), (2,3) -- adjacent j cols
#pragma unroll
        for (int pr = 0; pr < 2; pr++) {
            const int e0 = pr * 2, e1 = e0 + 1;
            const int p0 = mt * 4 + e0, p1 = mt * 4 + e1;
            __half2 i2 = __floats2half2_rn(d[0][e0], d[0][e1]);
            __half2 f2 = __floats2half2_rn(d[1][e0], d[1][e1]);
            __half2 g2 = __floats2half2_rn(d[2][e0], d[2][e1]);
            __half2 o2 = __floats2half2_rn(d[3][e0], d[3][e1]);
            __half2 sf2 = __hfma2(tanh_h2(__hmul2(f2, hhalf)), hhalf, hhalf);
            __half2 si2 = __hfma2(tanh_h2(__hmul2(i2, hhalf)), hhalf, hhalf);
            __half2 so2 = __hfma2(tanh_h2(__hmul2(o2, hhalf)), hhalf, hhalf);
            __half2 tg2 = tanh_h2(g2);
            __half2 pp2 = __hmul2(si2, tg2);
            float2 sff = __half22float2(sf2);
            float2 ppf = __half22float2(pp2);
            float c0 = fmaf(sff.x, c_[p0], ppf.x);
            float c1 = fmaf(sff.y, c_[p1], ppf.y);
            c_[p0] = c0; c_[p1] = c1;
            __half2 tc2 = tanh_h2(__floats2half2_rn(c0, c1));
            __half2 hv2 = __hmul2(so2, tc2);
            float2 hf = __half22float2(hv2);
            hr[p0] = hf.x; hr[p1] = hf.y;
        }
    }
}

// ---------------------------------------------------------------------------
// Kernel 2: fp16 mma.sync LSTM + attention.  64 seq/CTA, 8 warps, 2 CTA/SM.
// ---------------------------------------------------------------------------
__global__ __launch_bounds__(256, 2) void lstm_mma_kernel(
    const float* __restrict__ x,
    const float* __restrict__ Wih,
    const float* __restrict__ Whh,
    const float* __restrict__ bih,
    const float* __restrict__ bhh,
    const float* __restrict__ attn_w,
    const float* __restrict__ attn_b)
{
    extern __shared__ char smc[];
    __half* As0 = (__half*)(smc + AS0_B);
    __half* As1 = (__half*)(smc + AS1_B);
    __half* xh  = (__half*)(smc + XH_B);
    float*  SP  = (float*)(smc + SP_B);
    float*  WN  = (float*)(smc + WN_B);
    float*  AW  = (float*)(smc + AW_B);

    const int tid  = threadIdx.x;
    const int w    = tid >> 5, lane = tid & 31;
    const int gq   = lane >> 2;
    const int tq   = lane & 3;
    const size_t seq0 = (size_t)blockIdx.x * NSEQ;

    {
        const float* xg = x + seq0 * (Tt * Ff);
        for (int i = tid; i < NSEQ * Tt * Ff; i += 256) {
            int s = i / (Tt * Ff);
            int r = i - s * (Tt * Ff);
            int t = r / Ff, f = r - t * Ff;
            xh[(t * NSEQ + s) * Ff + f] = __float2half(xg[i]);
        }
    }
    {
        uint4 z4 = {0u,0u,0u,0u};
        uint4* ap = (uint4*)As0;
        for (int i = tid; i < 2 * NSEQ * ASTH * 2 / 16; i += 256) ap[i] = z4;
    }
    __syncthreads();
    if (tid < NSEQ) {
        As0[tid * ASTH + 69] = __float2half(1.0f);
        As1[tid * ASTH + 69] = __float2half(1.0f);
        const __half* xr = xh + tid * Ff;
#pragma unroll
        for (int f = 0; f < Ff; f++) As0[tid * ASTH + 64 + f] = xr[f];
    }
    if (tid < 64) AW[tid] = attn_w[tid];

    uint32_t bf[4][5][2];
#pragma unroll
    for (int nt = 0; nt < 4; nt++) {
        const int g = nt * 64 + w * 8 + gq;
        const float bias_g = bih[g] + bhh[g];
#pragma unroll
        for (int kt = 0; kt < 5; kt++) {
#pragma unroll
            for (int hb = 0; hb < 2; hb++) {
                int k0 = kt * 16 + 2 * tq + hb * 8;
                float v0, v1;
                {
                    int k = k0;
                    if (k < 64)       v0 = Whh[g * Hh + k];
                    else if (k < 69)  v0 = Wih[g * Ff + (k - 64)];
                    else if (k == 69) v0 = bias_g;
                    else              v0 = 0.f;
                }
                {
                    int k = k0 + 1;
                    if (k < 64)       v1 = Whh[g * Hh + k];
                    else if (k < 69)  v1 = Wih[g * Ff + (k - 64)];
                    else if (k == 69) v1 = bias_g;
                    else              v1 = 0.f;
                }
                bf[nt][kt][hb] = pack_h2(v0, v1);
            }
        }
    }
    __syncthreads();

    float c_[16], acc_[16], hr[16];
#pragma unroll
    for (int p = 0; p < 16; p++) { c_[p] = 0.f; acc_[p] = 0.f; }
    float Z = 0.f;
    const float ab0 = attn_b[0];
    const float awA = AW[w * 8 + 2 * tq];
    const float awB = AW[w * 8 + 2 * tq + 1];

    const uint32_t as_u = smem_u32(As0);
    const uint32_t lm0 = as_u + (uint32_t)(lane & 15) * (ASTH * 2)
                       + (uint32_t)((lane >> 4) * 16);
    const uint32_t lm1 = lm0 + (AS1_B - AS0_B);
    const int rot = w & 3;

    for (int t = 0; t < Tt; t++) {
        const uint32_t lm_cur = (t & 1) ? lm1 : lm0;
        __half* Awr = (t & 1) ? As0 : As1;

        switch (rot) {
            case 0: lstm_phase1<0>(lm_cur, bf, c_, hr); break;
            case 1: lstm_phase1<1>(lm_cur, bf, c_, hr); break;
            case 2: lstm_phase1<2>(lm_cur, bf, c_, hr); break;
            default: lstm_phase1<3>(lm_cur, bf, c_, hr); break;
        }

#pragma unroll
        for (int mt = 0; mt < 4; mt++) {
#pragma unroll
            for (int pr = 0; pr < 2; pr++) {
                const int p = mt * 4 + pr * 2;
                const int seqr = mt * 16 + gq + pr * 8;
                *(__half2*)(Awr + seqr * ASTH + w * 8 + 2 * tq) =
                    __floats2half2_rn(hr[p], hr[p + 1]);
            }
        }
        if (t < Tt - 1 && tid < NSEQ) {
            const __half* xr = xh + ((t + 1) * NSEQ + tid) * Ff;
#pragma unroll
            for (int f = 0; f < Ff; f++) Awr[tid * ASTH + 64 + f] = xr[f];
        }
#pragma unroll
        for (int mt = 0; mt < 4; mt++) {
#pragma unroll
            for (int pr = 0; pr < 2; pr++) {
                float v = hr[mt * 4 + pr * 2] * awA + hr[mt * 4 + pr * 2 + 1] * awB;
                v += __shfl_xor_sync(0xffffffffu, v, 1);
                v += __shfl_xor_sync(0xffffffffu, v, 2);
                if (tq == 0) SP[w * NSEQ + mt * 16 + gq + pr * 8] = v;
            }
        }
        __syncthreads();
        if (tid < NSEQ) {
            float s = ab0;
#pragma unroll
            for (int ww = 0; ww < 8; ww++) s += SP[ww * NSEQ + tid];
            float e = __expf(tanha(s));
            Z += e;
            WN[tid] = e;
        }
        __syncthreads();
#pragma unroll
        for (int p = 0; p < 16; p++) {
            const int mt = p >> 2, pr = (p >> 1) & 1;
            acc_[p] = fmaf(WN[mt * 16 + gq + pr * 8], hr[p], acc_[p]);
        }
    }

    if (tid < NSEQ) WN[tid] = 1.0f / Z;
    __syncthreads();
#pragma unroll
    for (int p = 0; p < 16; p++) {
        const int mt = p >> 2, pr = (p >> 1) & 1, pc = p & 1;
        const int seqr = mt * 16 + gq + pr * 8;
        const int j = w * 8 + 2 * tq + pc;
        g_eold[(seq0 + seqr) * Hh + j] = acc_[p] * WN[seqr];
    }
}

// ---------------------------------------------------------------------------
// Kernel 3: GNN, fp16 MMA + ldmatrix (round-12, passing)
// ---------------------------------------------------------------------------
__global__ __launch_bounds__(256, 2) void gnn_mma_kernel(
    const float* __restrict__ pred_w,
    const float* __restrict__ pred_b,
    float* __restrict__ out)
{
    extern __shared__ char gsc[];
    __half* Ejs = (__half*)(gsc + G_EJ_B);
    __half* Sh  = (__half*)(gsc + G_SH_B);
    float*  CF  = (float*)(gsc + G_CF_B);

    const int tid = threadIdx.x;
    const int w = tid >> 5, lane = tid & 31;
    const int gq = lane >> 2, tq = lane & 3;
    const int b  = blockIdx.y;
    const int i0 = blockIdx.x * 128;
    const float* eob = g_eold + (size_t)b * Nn * Hh;

    uint32_t ae[4][4];
    {
        const float* r0 = eob + (size_t)(i0 + w * 16 + gq) * Hh;
        const float* r1 = r0 + 8 * Hh;
#pragma unroll
        for (int kt = 0; kt < 4; kt++) {
            int k0 = kt * 16 + 2 * tq;
            ae[kt][0] = pack_h2(r0[k0],     r0[k0 + 1]);
            ae[kt][1] = pack_h2(r1[k0],     r1[k0 + 1]);
            ae[kt][2] = pack_h2(r0[k0 + 8], r0[k0 + 9]);
            ae[kt][3] = pack_h2(r1[k0 + 8], r1[k0 + 9]);
        }
    }
    float d2[8][4];
#pragma unroll
    for (int nt = 0; nt < 8; nt++) { d2[nt][0]=0.f; d2[nt][1]=0.f; d2[nt][2]=0.f; d2[nt][3]=0.f; }

    const uint32_t ej_u = smem_u32(Ejs);
    const uint32_t sh_u = smem_u32(Sh);
    const int lr = lane & 7, lt = lane >> 3;
    const uint32_t b1_base = ej_u + (uint32_t)lr * (EJH_ST * 2) + (uint32_t)lt * 16;
    const uint32_t a2_base = sh_u
        + (uint32_t)(w * 16 + lr + (lt & 1) * 8) * (SH_ST * 2) + (uint32_t)(lt >> 1) * 16;
    const uint32_t b2_base = ej_u
        + (uint32_t)(lr + (lt & 1) * 8) * (EJH_ST * 2) + (uint32_t)(lt >> 1) * 16;

    for (int j0 = 0; j0 < Nn; j0 += GJT) {
        __syncthreads();
        {
            int j = tid >> 2, qq = tid & 3;
            const float4* src = (const float4*)(eob + (size_t)(j0 + j) * Hh + qq * 16);
            float4 v0 = src[0], v1 = src[1], v2 = src[2], v3 = src[3];
            __half2* dst = (__half2*)(Ejs + j * EJH_ST + qq * 16);
            dst[0] = __floats2half2_rn(v0.x, v0.y);
            dst[1] = __floats2half2_rn(v0.z, v0.w);
            dst[2] = __floats2half2_rn(v1.x, v1.y);
            dst[3] = __floats2half2_rn(v1.z, v1.w);
            dst[4] = __floats2half2_rn(v2.x, v2.y);
            dst[5] = __floats2half2_rn(v2.z, v2.w);
            dst[6] = __floats2half2_rn(v3.x, v3.y);
            dst[7] = __floats2half2_rn(v3.z, v3.w);
        }
        for (int idx = tid; idx < 128 * 16; idx += 256) {
            int i = idx >> 4, jq = idx & 15;
            *(float4*)(CF + i * CF_ST + jq * 4) =
                *(const float4*)(g_coef + (size_t)(i0 + i) * Nn + j0 + jq * 4);
        }
        __syncthreads();

        float d1[8][4];
#pragma unroll
        for (int nt = 0; nt < 8; nt++) { d1[nt][0]=0.f; d1[nt][1]=0.f; d1[nt][2]=0.f; d1[nt][3]=0.f; }
#pragma unroll
        for (int ktp = 0; ktp < 2; ktp++) {
#pragma unroll
            for (int nt = 0; nt < 8; nt++) {
                uint32_t bb[4];
                LDSM4(bb, b1_base + (uint32_t)nt * 8 * (EJH_ST * 2) + (uint32_t)ktp * 64);
                MMA_F16(d1[nt], ae[ktp * 2],     bb);
                MMA_F16(d1[nt], ae[ktp * 2 + 1], bb + 2);
            }
        }
        {
            const float* c0p = CF + (w * 16 + gq) * CF_ST;
            const float* c1p = c0p + 8 * CF_ST;
            __half* s0p = Sh + (w * 16 + gq) * SH_ST;
            __half* s1p = s0p + 8 * SH_ST;
#pragma unroll
            for (int nt = 0; nt < 8; nt++) {
                int cc = nt * 8 + 2 * tq;
                float2 c0 = *(const float2*)(c0p + cc);
                float2 c1 = *(const float2*)(c1p + cc);
                *(__half2*)(s0p + cc) = __floats2half2_rn(d1[nt][0] * c0.x, d1[nt][1] * c0.y);
                *(__half2*)(s1p + cc) = __floats2half2_rn(d1[nt][2] * c1.x, d1[nt][3] * c1.y);
            }
        }
        __syncwarp();

#pragma unroll
        for (int ktj = 0; ktj < 4; ktj++) {
            uint32_t aa[4];
            LDSM4(aa, a2_base + (uint32_t)ktj * 32);
#pragma unroll
            for (int ntp = 0; ntp < 4; ntp++) {
                uint32_t bb[4];
                LDSM4T(bb, b2_base + (uint32_t)ktj * 16 * (EJH_ST * 2) + (uint32_t)ntp * 32);
                MMA_F16(d2[ntp * 2],     aa, bb);
                MMA_F16(d2[ntp * 2 + 1], aa, bb + 2);
            }
        }
    }

    const int i_a = i0 + w * 16 + gq;
    const int i_b = i_a + 8;
    const float inv0 = 1.0f / g_deg[i_a];
    const float inv1 = 1.0f / g_deg[i_b];
    float p0 = 0.f, p1 = 0.f;
#pragma unroll
    for (int kt = 0; kt < 4; kt++) {
        int k0 = kt * 16 + 2 * tq;
        float wa = pred_w[k0], wb = pred_w[k0 + 1];
        float wc = pred_w[k0 + 8], wd = pred_w[k0 + 9];
        float2 v;
        v = __half22float2(*(__half2*)&ae[kt][0]); p0 = fmaf(v.x, wa, fmaf(v.y, wb, p0));
        v = __half22float2(*(__half2*)&ae[kt][2]); p0 = fmaf(v.x, wc, fmaf(v.y, wd, p0));
        v = __half22float2(*(__half2*)&ae[kt][1]); p1 = fmaf(v.x, wa, fmaf(v.y, wb, p1));
        v = __half22float2(*(__half2*)&ae[kt][3]); p1 = fmaf(v.x, wc, fmaf(v.y, wd, p1));
    }
#pragma unroll
    for (int nt = 0; nt < 8; nt++) {
        float wA = pred_w[64 + nt * 8 + 2 * tq];
        float wB = pred_w[64 + nt * 8 + 2 * tq + 1];
        p0 = fmaf(d2[nt][0] * inv0, wA, p0);
        p0 = fmaf(d2[nt][1] * inv0, wB, p0);
        p1 = fmaf(d2[nt][2] * inv1, wA, p1);
        p1 = fmaf(d2[nt][3] * inv1, wB, p1);
    }
    p0 += __shfl_xor_sync(0xffffffffu, p0, 1);
    p0 += __shfl_xor_sync(0xffffffffu, p0, 2);
    p1 += __shfl_xor_sync(0xffffffffu, p1, 1);
    p1 += __shfl_xor_sync(0xffffffffu, p1, 2);
    if (tq == 0) {
        out[(size_t)b * Nn + i_a] = p0 + pred_b[0];
        out[(size_t)b * Nn + i_b] = p1 + pred_b[0];
    }
}

// ---------------------------------------------------------------------------
extern "C" void kernel_launch(void* const* d_in, const int* in_sizes, int n_in,
                              void* d_out, int out_size)
{
    const float* x      = (const float*)d_in[0];
    const float* A      = (const float*)d_in[1];
    const float* Wih    = (const float*)d_in[2];
    const float* Whh    = (const float*)d_in[3];
    const float* bih    = (const float*)d_in[4];
    const float* bhh    = (const float*)d_in[5];
    const float* attn_w = (const float*)d_in[6];
    const float* attn_b = (const float*)d_in[7];
    const float* gnn_w  = (const float*)d_in[8];
    const float* gnn_b  = (const float*)d_in[9];
    const float* pred_w = (const float*)d_in[10];
    const float* pred_b = (const float*)d_in[11];
    float* out = (float*)d_out;

    cudaFuncSetAttribute(lstm_mma_kernel,
                         cudaFuncAttributeMaxDynamicSharedMemorySize, DYN_SMEM);
    cudaFuncSetAttribute(gnn_mma_kernel,
                         cudaFuncAttributeMaxDynamicSharedMemorySize, GNN_SMEM);

    lstm_mma_kernel<<<BN / NSEQ, 256, DYN_SMEM>>>(x, Wih, Whh, bih, bhh, attn_w, attn_b);
    prep_kernel<<<Nn, 256>>>(A, gnn_w, gnn_b);
    gnn_mma_kernel<<<dim3(Nn / 128, Bb), 256, GNN_SMEM>>>(pred_w, pred_b, out);
}